// round 4
// baseline (speedup 1.0000x reference)
#include <cuda_runtime.h>
#include <cstdint>
#include <cstddef>

#define E_MAX 8000000
#define N_MAX 500000

// ---- static device scratch (naturally aligned via element types) ----
__device__ uint2  g_edges[E_MAX];            // 64MB packed (src,dst)
__device__ float  g_dinv [N_MAX];            // 2MB
__device__ float4 g_xs   [N_MAX * 3];        // 24MB  x*dinv, 12 floats/row
__device__ float4 g_acc1 [N_MAX * 3];        // 24MB
__device__ float2 g_gs   [N_MAX];            // 4MB
__device__ float2 g_acc2 [N_MAX];            // 4MB
__device__ int    g_is64;                    // edge dtype flag

// 0) detect edge_index dtype: int64 hi-words (odd 32-bit lanes) are all zero
__global__ void k_detect(const int* __restrict__ ei_raw) {
    if (blockIdx.x == 0 && threadIdx.x == 0) {
        int odd_zero = 0;
        for (int k = 0; k < 64; k++) odd_zero += (ei_raw[2 * k + 1] == 0);
        g_is64 = (odd_zero >= 60) ? 1 : 0;
    }
}

// 1) deg init: self-loop contributes 1 to every node
__global__ void k_init_deg(int N) {
    int i = blockIdx.x * blockDim.x + threadIdx.x;
    if (i < N) g_dinv[i] = 1.0f;
}

// 2) degree count + convert to packed uint2 (dtype-agnostic, clamped)
__global__ void k_deg_convert(const void* __restrict__ eiv, int E, int N) {
    int e = blockIdx.x * blockDim.x + threadIdx.x;
    if (e >= E) return;
    unsigned s, d;
    if (g_is64) {
        const long long* ei = (const long long*)eiv;
        s = (unsigned)ei[e];
        d = (unsigned)ei[(size_t)E + e];
    } else {
        const int* ei = (const int*)eiv;
        s = (unsigned)ei[e];
        d = (unsigned)ei[(size_t)E + e];
    }
    if (s >= (unsigned)N) s = 0;
    if (d >= (unsigned)N) d = 0;
    g_edges[e] = make_uint2(s, d);
    atomicAdd(&g_dinv[d], 1.0f);
}

// 3) dinv = rsqrt(deg); xs = x * dinv (padded); acc1 init = self-loop term
__global__ void k_prep(const float* __restrict__ x, int N) {
    int i = blockIdx.x * blockDim.x + threadIdx.x;
    if (i >= N) return;
    float dv = rsqrtf(g_dinv[i]);
    g_dinv[i] = dv;
    const float* xr = x + (size_t)i * 10;
    float v[12];
#pragma unroll
    for (int k = 0; k < 10; k++) v[k] = xr[k] * dv;
    v[10] = 0.0f; v[11] = 0.0f;
#pragma unroll
    for (int q = 0; q < 3; q++) {
        float4 p = make_float4(v[4*q], v[4*q+1], v[4*q+2], v[4*q+3]);
        g_xs  [(size_t)i * 3 + q] = p;
        g_acc1[(size_t)i * 3 + q] = p;
    }
}

// 4) layer-1 aggregation: acc1[dst] += xs[src] (scalar atomics, 10/edge)
__global__ void k_agg1(int E) {
    int e = blockIdx.x * blockDim.x + threadIdx.x;
    if (e >= E) return;
    uint2 ed = g_edges[e];
    const float4* sp = &g_xs[(size_t)ed.x * 3];
    float4 a = __ldg(sp);
    float4 b = __ldg(sp + 1);
    float4 c = __ldg(sp + 2);
    float* dp = (float*)&g_acc1[(size_t)ed.y * 3];
    atomicAdd(dp + 0, a.x);
    atomicAdd(dp + 1, a.y);
    atomicAdd(dp + 2, a.z);
    atomicAdd(dp + 3, a.w);
    atomicAdd(dp + 4, b.x);
    atomicAdd(dp + 5, b.y);
    atomicAdd(dp + 6, b.z);
    atomicAdd(dp + 7, b.w);
    atomicAdd(dp + 8, c.x);
    atomicAdd(dp + 9, c.y);
}

// 5) fused node kernel: f = dinv*acc1 ; h = relu(f@W1+b1) ; g = h@W2 ;
//    gs = g*dinv ; acc2 init = gs (self loop)
__global__ void k_layer1(const float* __restrict__ W1, const float* __restrict__ b1,
                         const float* __restrict__ W2, int N) {
    __shared__ float sW1[350];  // [10][35]
    __shared__ float sB1[35];
    __shared__ float sW2[70];   // [35][2]
    int t = threadIdx.x;
    for (int idx = t; idx < 350; idx += blockDim.x) sW1[idx] = W1[idx];
    for (int idx = t; idx < 70;  idx += blockDim.x) sW2[idx] = W2[idx];
    for (int idx = t; idx < 35;  idx += blockDim.x) sB1[idx] = b1[idx];
    __syncthreads();

    int i = blockIdx.x * blockDim.x + t;
    if (i >= N) return;
    float dv = g_dinv[i];
    float4 a0 = g_acc1[(size_t)i * 3 + 0];
    float4 a1 = g_acc1[(size_t)i * 3 + 1];
    float4 a2 = g_acc1[(size_t)i * 3 + 2];
    float f[10];
    f[0] = a0.x * dv; f[1] = a0.y * dv; f[2] = a0.z * dv; f[3] = a0.w * dv;
    f[4] = a1.x * dv; f[5] = a1.y * dv; f[6] = a1.z * dv; f[7] = a1.w * dv;
    f[8] = a2.x * dv; f[9] = a2.y * dv;

    float g0 = 0.0f, g1 = 0.0f;
#pragma unroll
    for (int j = 0; j < 35; j++) {
        float h = sB1[j];
#pragma unroll
        for (int k = 0; k < 10; k++) h = fmaf(f[k], sW1[k * 35 + j], h);
        h = fmaxf(h, 0.0f);
        g0 = fmaf(h, sW2[2 * j],     g0);
        g1 = fmaf(h, sW2[2 * j + 1], g1);
    }
    float2 gs = make_float2(g0 * dv, g1 * dv);
    g_gs[i]   = gs;
    g_acc2[i] = gs;
}

// 6) layer-2 aggregation: acc2[dst] += gs[src]
__global__ void k_agg2(int E) {
    int e = blockIdx.x * blockDim.x + threadIdx.x;
    if (e >= E) return;
    uint2 ed = g_edges[e];
    float2 v = __ldg(&g_gs[ed.x]);
    float* dp = (float*)&g_acc2[ed.y];
    atomicAdd(dp + 0, v.x);
    atomicAdd(dp + 1, v.y);
}

// 7) logits = dinv*acc2 + b2 ; log_softmax over 2 classes
__global__ void k_out(const float* __restrict__ b2, float* __restrict__ out, int N) {
    int i = blockIdx.x * blockDim.x + threadIdx.x;
    if (i >= N) return;
    float dv = g_dinv[i];
    float2 a = g_acc2[i];
    float z0 = fmaf(a.x, dv, b2[0]);
    float z1 = fmaf(a.y, dv, b2[1]);
    float m  = fmaxf(z0, z1);
    float lse = m + logf(expf(z0 - m) + expf(z1 - m));
    out[2 * i]     = z0 - lse;
    out[2 * i + 1] = z1 - lse;
}

extern "C" void kernel_launch(void* const* d_in, const int* in_sizes, int n_in,
                              void* d_out, int out_size) {
    // Bind inputs by element count (ordering-proof).
    const float* x  = nullptr; const void* ei = nullptr;
    const float* W1 = nullptr; const float* b1 = nullptr;
    const float* W2 = nullptr; const float* b2 = nullptr;
    int x_elems = 0, e_elems = 0;
    for (int i = 0; i < n_in; i++) {
        int s = in_sizes[i];
        if      (s == 350) W1 = (const float*)d_in[i];
        else if (s == 35)  b1 = (const float*)d_in[i];
        else if (s == 70)  W2 = (const float*)d_in[i];
        else if (s == 2)   b2 = (const float*)d_in[i];
        else if (s == 16000000) { ei = d_in[i]; e_elems = s; }
        else if (s == 5000000)  { x  = (const float*)d_in[i]; x_elems = s; }
    }
    float* out = (float*)d_out;
    int N = x_elems / 10;
    int E = e_elems / 2;

    const int TB = 256;
    int gN = (N + TB - 1) / TB;
    int gE = (E + TB - 1) / TB;

    k_detect     <<<1, 32>>>((const int*)ei);
    k_init_deg   <<<gN, TB>>>(N);
    k_deg_convert<<<gE, TB>>>(ei, E, N);
    k_prep       <<<gN, TB>>>(x, N);
    k_agg1       <<<gE, TB>>>(E);
    k_layer1     <<<gN, TB>>>(W1, b1, W2, N);
    k_agg2       <<<gE, TB>>>(E);
    k_out        <<<gN, TB>>>(b2, out, N);
}

// round 5
// speedup vs baseline: 1.9763x; 1.9763x over previous
#include <cuda_runtime.h>
#include <cstdint>
#include <cstddef>

#define N_MAX  500000
#define E_MAX  8000000
#define NB_MAX 2048   // scan blocks: (500000+255)/256 = 1954 <= 2048

// ---- static device scratch ----
__device__ int      g_cnt   [N_MAX];       // neighbor counts (no self-loop)
__device__ int      g_rowptr[N_MAX + 1];
__device__ int      g_cursor[N_MAX];
__device__ int      g_partial[NB_MAX];
__device__ unsigned g_csr   [E_MAX];       // src ids grouped by dst (32MB)
__device__ float    g_dinv  [N_MAX];
__device__ float4   g_xs    [N_MAX * 3];   // x * dinv[src], 12-padded (24MB)
__device__ float2   g_gs    [N_MAX];       // layer-2 messages (4MB)
__device__ int      g_is64;

// 0) detect edge_index dtype (int64 hi-words are ~all zero for idx < 500k)
__global__ void k_detect(const int* __restrict__ ei_raw) {
    if (threadIdx.x == 0) {
        int odd_zero = 0;
        for (int k = 0; k < 64; k++) odd_zero += (ei_raw[2 * k + 1] == 0);
        g_is64 = (odd_zero >= 60) ? 1 : 0;
    }
}

// 1) zero counts
__global__ void k_zero(int N) {
    int i = blockIdx.x * blockDim.x + threadIdx.x;
    if (i < N) g_cnt[i] = 0;
}

// 2) count in-degree (dst only)
__global__ void k_count(const void* __restrict__ eiv, int E, int N) {
    int e = blockIdx.x * blockDim.x + threadIdx.x;
    if (e >= E) return;
    unsigned d = g_is64 ? (unsigned)((const long long*)eiv)[(size_t)E + e]
                        : (unsigned)((const int*)eiv)[(size_t)E + e];
    if (d >= (unsigned)N) d = 0;
    atomicAdd(&g_cnt[d], 1);
}

// 3a) per-block exclusive scan + block sums
__global__ void k_scan1(int N) {
    __shared__ int sh[256];
    int i = blockIdx.x * 256 + threadIdx.x;
    int v = (i < N) ? g_cnt[i] : 0;
    sh[threadIdx.x] = v;
    __syncthreads();
#pragma unroll
    for (int off = 1; off < 256; off <<= 1) {
        int t = 0;
        if (threadIdx.x >= off) t = sh[threadIdx.x - off];
        __syncthreads();
        if (threadIdx.x >= off) sh[threadIdx.x] += t;
        __syncthreads();
    }
    if (i < N) g_rowptr[i] = sh[threadIdx.x] - v;   // exclusive within block
    if (threadIdx.x == 255) g_partial[blockIdx.x] = sh[255];
}

// 3b) scan the block sums (single block, 1024 threads, 2 elems each)
__global__ void k_scan2(int nb) {
    __shared__ int sh[NB_MAX];
    for (int i = threadIdx.x; i < NB_MAX; i += 1024)
        sh[i] = (i < nb) ? g_partial[i] : 0;
    __syncthreads();
    for (int off = 1; off < NB_MAX; off <<= 1) {
        int i0 = threadIdx.x, i1 = threadIdx.x + 1024;
        int t0 = (i0 >= off) ? sh[i0 - off] : 0;
        int t1 = (i1 >= off) ? sh[i1 - off] : 0;
        __syncthreads();
        sh[i0] += t0;
        sh[i1] += t1;
        __syncthreads();
    }
    // exclusive result
    for (int i = threadIdx.x; i < nb; i += 1024)
        g_partial[i] = (i == 0) ? 0 : sh[i - 1];
}

// 3c) add block offsets; init cursor; set rowptr[N]=E
__global__ void k_scan3(int N, int E) {
    int i = blockIdx.x * 256 + threadIdx.x;
    if (i < N) {
        int v = g_rowptr[i] + g_partial[blockIdx.x];
        g_rowptr[i] = v;
        g_cursor[i] = v;
    }
    if (i == 0) g_rowptr[N] = E;
}

// 4) scatter src into dst-grouped CSR
__global__ void k_scatter(const void* __restrict__ eiv, int E, int N) {
    int e = blockIdx.x * blockDim.x + threadIdx.x;
    if (e >= E) return;
    unsigned s, d;
    if (g_is64) {
        const long long* p = (const long long*)eiv;
        s = (unsigned)p[e];
        d = (unsigned)p[(size_t)E + e];
    } else {
        const int* p = (const int*)eiv;
        s = (unsigned)p[e];
        d = (unsigned)p[(size_t)E + e];
    }
    if (s >= (unsigned)N) s = 0;
    if (d >= (unsigned)N) d = 0;
    int pos = atomicAdd(&g_cursor[d], 1);
    g_csr[pos] = s;
}

// 5) dinv = rsqrt(deg+1); xs = x * dinv (12-padded)
__global__ void k_prep(const float* __restrict__ x, int N) {
    int i = blockIdx.x * blockDim.x + threadIdx.x;
    if (i >= N) return;
    float dv = rsqrtf((float)g_cnt[i] + 1.0f);
    g_dinv[i] = dv;
    const float* xr = x + (size_t)i * 10;
    float v[12];
#pragma unroll
    for (int k = 0; k < 10; k++) v[k] = xr[k] * dv;
    v[10] = 0.0f; v[11] = 0.0f;
#pragma unroll
    for (int q = 0; q < 3; q++)
        g_xs[(size_t)i * 3 + q] = make_float4(v[4*q], v[4*q+1], v[4*q+2], v[4*q+3]);
}

// 6) fused layer 1: gather-sum xs over CSR + self, scale, MLP (10->35->2), scale
__global__ void k_fused1(const float* __restrict__ W1, const float* __restrict__ b1,
                         const float* __restrict__ W2, int N) {
    __shared__ float sW1[350];  // [10][35]
    __shared__ float sB1[35];
    __shared__ float sW2[70];   // [35][2]
    int t = threadIdx.x;
    for (int idx = t; idx < 350; idx += blockDim.x) sW1[idx] = W1[idx];
    for (int idx = t; idx < 70;  idx += blockDim.x) sW2[idx] = W2[idx];
    for (int idx = t; idx < 35;  idx += blockDim.x) sB1[idx] = b1[idx];
    __syncthreads();

    int i = blockIdx.x * blockDim.x + t;
    if (i >= N) return;

    float4 s0 = g_xs[(size_t)i * 3 + 0];   // self-loop term
    float4 s1 = g_xs[(size_t)i * 3 + 1];
    float4 s2 = g_xs[(size_t)i * 3 + 2];
    int beg = g_rowptr[i], end = g_rowptr[i + 1];
    for (int j = beg; j < end; j++) {
        unsigned src = g_csr[j];
        const float4* sp = &g_xs[(size_t)src * 3];
        float4 a = __ldg(sp);
        float4 b = __ldg(sp + 1);
        float4 c = __ldg(sp + 2);
        s0.x += a.x; s0.y += a.y; s0.z += a.z; s0.w += a.w;
        s1.x += b.x; s1.y += b.y; s1.z += b.z; s1.w += b.w;
        s2.x += c.x; s2.y += c.y;
    }
    float dv = g_dinv[i];
    float f[10];
    f[0] = s0.x * dv; f[1] = s0.y * dv; f[2] = s0.z * dv; f[3] = s0.w * dv;
    f[4] = s1.x * dv; f[5] = s1.y * dv; f[6] = s1.z * dv; f[7] = s1.w * dv;
    f[8] = s2.x * dv; f[9] = s2.y * dv;

    float g0 = 0.0f, g1 = 0.0f;
#pragma unroll
    for (int j = 0; j < 35; j++) {
        float h = sB1[j];
#pragma unroll
        for (int k = 0; k < 10; k++) h = fmaf(f[k], sW1[k * 35 + j], h);
        h = fmaxf(h, 0.0f);
        g0 = fmaf(h, sW2[2 * j],     g0);
        g1 = fmaf(h, sW2[2 * j + 1], g1);
    }
    g_gs[i] = make_float2(g0 * dv, g1 * dv);
}

// 7) fused layer 2 + log_softmax: gather-sum gs + self, scale, +b2, lsm, out
__global__ void k_fused2(const float* __restrict__ b2, float* __restrict__ out, int N) {
    int i = blockIdx.x * blockDim.x + threadIdx.x;
    if (i >= N) return;
    float2 acc = g_gs[i];                  // self-loop term
    int beg = g_rowptr[i], end = g_rowptr[i + 1];
    for (int j = beg; j < end; j++) {
        float2 v = __ldg(&g_gs[g_csr[j]]);
        acc.x += v.x;
        acc.y += v.y;
    }
    float dv = g_dinv[i];
    float z0 = fmaf(acc.x, dv, b2[0]);
    float z1 = fmaf(acc.y, dv, b2[1]);
    float m  = fmaxf(z0, z1);
    float lse = m + logf(expf(z0 - m) + expf(z1 - m));
    out[2 * i]     = z0 - lse;
    out[2 * i + 1] = z1 - lse;
}

extern "C" void kernel_launch(void* const* d_in, const int* in_sizes, int n_in,
                              void* d_out, int out_size) {
    // Bind inputs by element count (ordering-proof).
    const float* x  = nullptr; const void* ei = nullptr;
    const float* W1 = nullptr; const float* b1 = nullptr;
    const float* W2 = nullptr; const float* b2 = nullptr;
    int x_elems = 0, e_elems = 0;
    for (int i = 0; i < n_in; i++) {
        int s = in_sizes[i];
        if      (s == 350) W1 = (const float*)d_in[i];
        else if (s == 35)  b1 = (const float*)d_in[i];
        else if (s == 70)  W2 = (const float*)d_in[i];
        else if (s == 2)   b2 = (const float*)d_in[i];
        else if (s == 16000000) { ei = d_in[i]; e_elems = s; }
        else if (s == 5000000)  { x  = (const float*)d_in[i]; x_elems = s; }
    }
    float* out = (float*)d_out;
    int N = x_elems / 10;
    int E = e_elems / 2;

    const int TB = 256;
    int gN = (N + TB - 1) / TB;
    int gE = (E + TB - 1) / TB;

    k_detect <<<1, 32>>>((const int*)ei);
    k_zero   <<<gN, TB>>>(N);
    k_count  <<<gE, TB>>>(ei, E, N);
    k_scan1  <<<gN, TB>>>(N);
    k_scan2  <<<1, 1024>>>(gN);
    k_scan3  <<<gN, TB>>>(N, E);
    k_scatter<<<gE, TB>>>(ei, E, N);
    k_prep   <<<gN, TB>>>(x, N);
    k_fused1 <<<gN, TB>>>(W1, b1, W2, N);
    k_fused2 <<<gN, TB>>>(b2, out, N);
}

// round 6
// speedup vs baseline: 2.1452x; 1.0855x over previous
#include <cuda_runtime.h>
#include <cuda_fp16.h>
#include <cstdint>
#include <cstddef>

#define N_MAX  500000
#define E_MAX  8000000
#define NB_MAX 2048   // scan blocks: (500000+255)/256 = 1954 <= 2048

// one 32B row per node: 10 features as fp16 (+pad). Exactly one L2 sector.
struct __align__(32) XRow { uint4 a; uint4 b; };

// ---- static device scratch ----
__device__ int      g_cnt   [N_MAX];
__device__ int      g_rowptr[N_MAX + 1];
__device__ int      g_cursor[N_MAX];
__device__ int      g_partial[NB_MAX];
__device__ unsigned g_csr   [E_MAX];       // src ids grouped by dst (32MB)
__device__ float    g_dinv  [N_MAX];
__device__ XRow     g_xsh   [N_MAX];       // x*dinv as fp16, 32B rows (16MB)
__device__ float2   g_gs    [N_MAX];       // layer-2 messages, fp32 (4MB)
__device__ int      g_is64;

// 0) detect edge_index dtype (int64 hi-words ~all zero for idx < 500k)
__global__ void k_detect(const int* __restrict__ ei_raw) {
    if (threadIdx.x == 0) {
        int odd_zero = 0;
        for (int k = 0; k < 64; k++) odd_zero += (ei_raw[2 * k + 1] == 0);
        g_is64 = (odd_zero >= 60) ? 1 : 0;
    }
}

// 1) zero counts
__global__ void k_zero(int N) {
    int i = blockIdx.x * blockDim.x + threadIdx.x;
    if (i < N) g_cnt[i] = 0;
}

// 2) count in-degree (dst only)
__global__ void k_count(const void* __restrict__ eiv, int E, int N) {
    int e = blockIdx.x * blockDim.x + threadIdx.x;
    if (e >= E) return;
    unsigned d = g_is64 ? (unsigned)((const long long*)eiv)[(size_t)E + e]
                        : (unsigned)((const int*)eiv)[(size_t)E + e];
    if (d >= (unsigned)N) d = 0;
    atomicAdd(&g_cnt[d], 1);
}

// 3a) per-block exclusive scan + block sums
__global__ void k_scan1(int N) {
    __shared__ int sh[256];
    int i = blockIdx.x * 256 + threadIdx.x;
    int v = (i < N) ? g_cnt[i] : 0;
    sh[threadIdx.x] = v;
    __syncthreads();
#pragma unroll
    for (int off = 1; off < 256; off <<= 1) {
        int t = 0;
        if (threadIdx.x >= off) t = sh[threadIdx.x - off];
        __syncthreads();
        if (threadIdx.x >= off) sh[threadIdx.x] += t;
        __syncthreads();
    }
    if (i < N) g_rowptr[i] = sh[threadIdx.x] - v;
    if (threadIdx.x == 255) g_partial[blockIdx.x] = sh[255];
}

// 3b) scan block sums (single block, 1024 threads, 2 elems each)
__global__ void k_scan2(int nb) {
    __shared__ int sh[NB_MAX];
    for (int i = threadIdx.x; i < NB_MAX; i += 1024)
        sh[i] = (i < nb) ? g_partial[i] : 0;
    __syncthreads();
    for (int off = 1; off < NB_MAX; off <<= 1) {
        int i0 = threadIdx.x, i1 = threadIdx.x + 1024;
        int t0 = (i0 >= off) ? sh[i0 - off] : 0;
        int t1 = (i1 >= off) ? sh[i1 - off] : 0;
        __syncthreads();
        sh[i0] += t0;
        sh[i1] += t1;
        __syncthreads();
    }
    for (int i = threadIdx.x; i < nb; i += 1024)
        g_partial[i] = (i == 0) ? 0 : sh[i - 1];
}

// 3c) add block offsets; init cursor; rowptr[N]=E
__global__ void k_scan3(int N, int E) {
    int i = blockIdx.x * 256 + threadIdx.x;
    if (i < N) {
        int v = g_rowptr[i] + g_partial[blockIdx.x];
        g_rowptr[i] = v;
        g_cursor[i] = v;
    }
    if (i == 0) g_rowptr[N] = E;
}

// 4) scatter src into dst-grouped CSR
__global__ void k_scatter(const void* __restrict__ eiv, int E, int N) {
    int e = blockIdx.x * blockDim.x + threadIdx.x;
    if (e >= E) return;
    unsigned s, d;
    if (g_is64) {
        const long long* p = (const long long*)eiv;
        s = (unsigned)p[e];
        d = (unsigned)p[(size_t)E + e];
    } else {
        const int* p = (const int*)eiv;
        s = (unsigned)p[e];
        d = (unsigned)p[(size_t)E + e];
    }
    if (s >= (unsigned)N) s = 0;
    if (d >= (unsigned)N) d = 0;
    int pos = atomicAdd(&g_cursor[d], 1);
    g_csr[pos] = s;
}

// 5) dinv = rsqrt(deg+1); xsh = fp16(x * dinv), one 32B row
__global__ void k_prep(const float* __restrict__ x, int N) {
    int i = blockIdx.x * blockDim.x + threadIdx.x;
    if (i >= N) return;
    float dv = rsqrtf((float)g_cnt[i] + 1.0f);
    g_dinv[i] = dv;
    const float* xr = x + (size_t)i * 10;
    __half h[12];
#pragma unroll
    for (int k = 0; k < 10; k++) h[k] = __float2half_rn(xr[k] * dv);
    h[10] = __float2half_rn(0.0f); h[11] = __float2half_rn(0.0f);
    uint4 a, b;
    a.x = *(const unsigned*)&h[0];
    a.y = *(const unsigned*)&h[2];
    a.z = *(const unsigned*)&h[4];
    a.w = *(const unsigned*)&h[6];
    b.x = *(const unsigned*)&h[8];
    b.y = *(const unsigned*)&h[10];
    b.z = 0u; b.w = 0u;
    g_xsh[i].a = a;
    g_xsh[i].b = b;
}

// 6) fused layer 1: gather-sum fp16 rows (1 sector/edge) + self, fp32 math,
//    MLP (10->35->2), scale
__global__ void k_fused1(const float* __restrict__ W1, const float* __restrict__ b1,
                         const float* __restrict__ W2, int N) {
    __shared__ float sW1[350];  // [10][35]
    __shared__ float sB1[35];
    __shared__ float sW2[70];   // [35][2]
    int t = threadIdx.x;
    for (int idx = t; idx < 350; idx += blockDim.x) sW1[idx] = W1[idx];
    for (int idx = t; idx < 70;  idx += blockDim.x) sW2[idx] = W2[idx];
    for (int idx = t; idx < 35;  idx += blockDim.x) sB1[idx] = b1[idx];
    __syncthreads();

    int i = blockIdx.x * blockDim.x + t;
    if (i >= N) return;

    float f[10];
    {   // self-loop term
        uint4 ua = g_xsh[i].a;
        unsigned ub = g_xsh[i].b.x;
        float2 p;
        p = __half22float2(*(const __half2*)&ua.x); f[0] = p.x; f[1] = p.y;
        p = __half22float2(*(const __half2*)&ua.y); f[2] = p.x; f[3] = p.y;
        p = __half22float2(*(const __half2*)&ua.z); f[4] = p.x; f[5] = p.y;
        p = __half22float2(*(const __half2*)&ua.w); f[6] = p.x; f[7] = p.y;
        p = __half22float2(*(const __half2*)&ub);   f[8] = p.x; f[9] = p.y;
    }
    int beg = g_rowptr[i], end = g_rowptr[i + 1];
    for (int j = beg; j < end; j++) {
        unsigned src = g_csr[j];
        uint4 ua = __ldg(&g_xsh[src].a);
        unsigned ub = __ldg((const unsigned*)&g_xsh[src].b);
        float2 p;
        p = __half22float2(*(const __half2*)&ua.x); f[0] += p.x; f[1] += p.y;
        p = __half22float2(*(const __half2*)&ua.y); f[2] += p.x; f[3] += p.y;
        p = __half22float2(*(const __half2*)&ua.z); f[4] += p.x; f[5] += p.y;
        p = __half22float2(*(const __half2*)&ua.w); f[6] += p.x; f[7] += p.y;
        p = __half22float2(*(const __half2*)&ub);   f[8] += p.x; f[9] += p.y;
    }
    float dv = g_dinv[i];
#pragma unroll
    for (int k = 0; k < 10; k++) f[k] *= dv;

    float g0 = 0.0f, g1 = 0.0f;
#pragma unroll
    for (int j = 0; j < 35; j++) {
        float h = sB1[j];
#pragma unroll
        for (int k = 0; k < 10; k++) h = fmaf(f[k], sW1[k * 35 + j], h);
        h = fmaxf(h, 0.0f);
        g0 = fmaf(h, sW2[2 * j],     g0);
        g1 = fmaf(h, sW2[2 * j + 1], g1);
    }
    g_gs[i] = make_float2(g0 * dv, g1 * dv);
}

// 7) fused layer 2 + log_softmax
__global__ void k_fused2(const float* __restrict__ b2, float* __restrict__ out, int N) {
    int i = blockIdx.x * blockDim.x + threadIdx.x;
    if (i >= N) return;
    float2 acc = g_gs[i];                  // self-loop term
    int beg = g_rowptr[i], end = g_rowptr[i + 1];
    for (int j = beg; j < end; j++) {
        float2 v = __ldg(&g_gs[g_csr[j]]);
        acc.x += v.x;
        acc.y += v.y;
    }
    float dv = g_dinv[i];
    float z0 = fmaf(acc.x, dv, b2[0]);
    float z1 = fmaf(acc.y, dv, b2[1]);
    float m  = fmaxf(z0, z1);
    float lse = m + logf(expf(z0 - m) + expf(z1 - m));
    out[2 * i]     = z0 - lse;
    out[2 * i + 1] = z1 - lse;
}

extern "C" void kernel_launch(void* const* d_in, const int* in_sizes, int n_in,
                              void* d_out, int out_size) {
    const float* x  = nullptr; const void* ei = nullptr;
    const float* W1 = nullptr; const float* b1 = nullptr;
    const float* W2 = nullptr; const float* b2 = nullptr;
    int x_elems = 0, e_elems = 0;
    for (int i = 0; i < n_in; i++) {
        int s = in_sizes[i];
        if      (s == 350) W1 = (const float*)d_in[i];
        else if (s == 35)  b1 = (const float*)d_in[i];
        else if (s == 70)  W2 = (const float*)d_in[i];
        else if (s == 2)   b2 = (const float*)d_in[i];
        else if (s == 16000000) { ei = d_in[i]; e_elems = s; }
        else if (s == 5000000)  { x  = (const float*)d_in[i]; x_elems = s; }
    }
    float* out = (float*)d_out;
    int N = x_elems / 10;
    int E = e_elems / 2;

    const int TB = 256;
    int gN = (N + TB - 1) / TB;
    int gE = (E + TB - 1) / TB;

    k_detect <<<1, 32>>>((const int*)ei);
    k_zero   <<<gN, TB>>>(N);
    k_count  <<<gE, TB>>>(ei, E, N);
    k_scan1  <<<gN, TB>>>(N);
    k_scan2  <<<1, 1024>>>(gN);
    k_scan3  <<<gN, TB>>>(N, E);
    k_scatter<<<gE, TB>>>(ei, E, N);
    k_prep   <<<gN, TB>>>(x, N);
    k_fused1 <<<gN, TB>>>(W1, b1, W2, N);
    k_fused2 <<<gN, TB>>>(b2, out, N);
}